// round 9
// baseline (speedup 1.0000x reference)
#include <cuda_runtime.h>

#define NN 100000
#define EE 800000
#define NEG 0.2f

// ---------------- scratch (device globals; no allocation allowed) ----------------
__device__ __align__(16) float g_h [NN * 128];   // projected features (both layers)
__device__ __align__(16) float g_x2[NN * 128];   // layer-1 output / layer-2 input
__device__ __align__(16) float g_el[NN * 4];
__device__ __align__(16) float g_er[NN * 4];
__device__ int g_deg [NN];
__device__ int g_off [NN];
__device__ int g_cur [NN];
__device__ int g_srcs[EE];                       // src node per CSR slot (dense: 3.2MB)
__device__ int g_tot;

// packed f32x2 FMA: 2 FMAs per issue slot (FFMA2) — PTX-only path
__device__ __forceinline__ void ffma2(float2& d, float2 a, float2 b) {
    asm("fma.rn.f32x2 %0, %1, %2, %0;"
        : "+l"(reinterpret_cast<unsigned long long&>(d))
        : "l"(reinterpret_cast<const unsigned long long&>(a)),
          "l"(reinterpret_cast<const unsigned long long&>(b)));
}
__device__ __forceinline__ float2 dup(float x) { return make_float2(x, x); }

// ---------------- CSR build (scan-free, compact) ----------------
__global__ void k_zero() {
    int i = blockIdx.x * blockDim.x + threadIdx.x;
    if (i < NN) g_deg[i] = 0;
    if (i == 0) g_tot = 0;
}

__global__ void k_count(const int* __restrict__ dst) {
    int e = blockIdx.x * blockDim.x + threadIdx.x;
    if (e < EE) atomicAdd(&g_deg[dst[e]], 1);
}

// warp-level exclusive scan + one global atomic per warp; CSR segment ORDER is
// arbitrary (only per-dst grouping matters), so no global scan needed.
__global__ void k_off() {
    int i = blockIdx.x * blockDim.x + threadIdx.x;
    int lane = threadIdx.x & 31;
    int v = (i < NN) ? g_deg[i] : 0;
    int x = v;
    #pragma unroll
    for (int o = 1; o < 32; o <<= 1) {
        int t = __shfl_up_sync(0xffffffffu, x, o);
        if (lane >= o) x += t;
    }
    int excl = x - v;
    int wsum = __shfl_sync(0xffffffffu, x, 31);
    int base = 0;
    if (lane == 31) base = atomicAdd(&g_tot, wsum);
    base = __shfl_sync(0xffffffffu, base, 31);
    if (i < NN) {
        g_off[i] = base + excl;
        g_cur[i] = base + excl;
    }
}

__global__ void k_fill(const int* __restrict__ src, const int* __restrict__ dst) {
    int e = blockIdx.x * blockDim.x + threadIdx.x;
    if (e < EE) {
        int p = atomicAdd(&g_cur[dst[e]], 1);
        g_srcs[p] = src[e];
    }
}
// after k_fill: g_off = start, g_cur = end of each node's CSR segment

// ---------------- GEMM + attention-logit epilogue (FFMA2 core) ----------------
// Block = 256 threads (8 warps), each warp computes 4 nodes x 128 cols.
// At the fp32 FMA-issue roofline (~49us per GEMM).
__global__ void k_gemm(const float* __restrict__ Xext, int useExt,
                       const float* __restrict__ W,
                       const float* __restrict__ al, const float* __restrict__ ar)
{
    __shared__ float4 xs[8][128];  // per-warp: 4 nodes' x packed per k
    const float* X = useExt ? Xext : g_x2;
    int w = threadIdx.x >> 5, lane = threadIdx.x & 31;
    int n0 = blockIdx.x * 32 + w * 4;

    float* xsf = (float*)&xs[w][0];
    #pragma unroll
    for (int r = 0; r < 4; r++) {
        int n = n0 + r;
        const float* xr = X + (long)n * 128;
        #pragma unroll
        for (int i = 0; i < 4; i++) {
            int c = lane + 32 * i;
            xsf[c * 4 + r] = (n < NN) ? xr[c] : 0.f;
        }
    }
    __syncwarp();

    float2 acc[4][2];  // [col][rowpair]
    #pragma unroll
    for (int c = 0; c < 4; c++) {
        acc[c][0] = make_float2(0.f, 0.f);
        acc[c][1] = make_float2(0.f, 0.f);
    }

    const float4* Wv = (const float4*)W;
    #pragma unroll 4
    for (int k = 0; k < 128; k++) {
        float4 wv = Wv[k * 32 + lane];
        float4 xk = xs[w][k];
        float2 x01 = make_float2(xk.x, xk.y);
        float2 x23 = make_float2(xk.z, xk.w);
        float2 w0 = dup(wv.x), w1 = dup(wv.y), w2 = dup(wv.z), w3 = dup(wv.w);
        ffma2(acc[0][0], x01, w0); ffma2(acc[0][1], x23, w0);
        ffma2(acc[1][0], x01, w1); ffma2(acc[1][1], x23, w1);
        ffma2(acc[2][0], x01, w2); ffma2(acc[2][1], x23, w2);
        ffma2(acc[3][0], x01, w3); ffma2(acc[3][1], x23, w3);
    }

    float av[4][4];
    #pragma unroll
    for (int c = 0; c < 4; c++) {
        av[0][c] = acc[c][0].x; av[1][c] = acc[c][0].y;
        av[2][c] = acc[c][1].x; av[3][c] = acc[c][1].y;
    }

    // epilogue: store h, and el/er = per-head dot(h, attn) via 8-lane reductions.
    float4 al4 = ((const float4*)al)[lane];
    float4 ar4 = ((const float4*)ar)[lane];
    int head = lane >> 3;
    #pragma unroll
    for (int r = 0; r < 4; r++) {
        int n = n0 + r;
        float pel = av[r][0]*al4.x + av[r][1]*al4.y + av[r][2]*al4.z + av[r][3]*al4.w;
        float per = av[r][0]*ar4.x + av[r][1]*ar4.y + av[r][2]*ar4.z + av[r][3]*ar4.w;
        #pragma unroll
        for (int o = 1; o < 8; o <<= 1) {
            pel += __shfl_xor_sync(0xffffffffu, pel, o);
            per += __shfl_xor_sync(0xffffffffu, per, o);
        }
        if (n < NN) {
            ((float4*)g_h)[n * 32 + lane] = make_float4(av[r][0], av[r][1], av[r][2], av[r][3]);
            if ((lane & 7) == 0) {
                g_el[n * 4 + head] = pel;
                g_er[n * 4 + head] = per;
            }
        }
    }
}

// ---------------- fused softmax + aggregation, single pass, 4-wide MLP ----------
// One warp per dst node; whole warp per edge (coalesced 512B h gather). Each lane
// computes its own head's exp. Normalization deferred: out = (sum ex*h)/(sum ex).
// No max-subtraction: logits O(1)-scale; fminf(.,80) guard is a no-op in practice
// and softmax is shift-invariant.
__global__ void __launch_bounds__(256, 6)
k_agg(const float* __restrict__ bias, float* __restrict__ outExt, int layer2)
{
    int d    = (blockIdx.x * blockDim.x + threadIdx.x) >> 5;
    int lane = threadIdx.x & 31;
    if (d >= NN) return;
    int hq = lane >> 3;
    int p0 = g_off[d], p1 = g_cur[d];

    float er_h = g_er[d * 4 + hq];

    float s_acc = 0.f;
    float2 A0 = make_float2(0.f, 0.f), A1 = A0;
    float2 B0 = A0, B1 = A0, C0 = A0, C1 = A0, D0 = A0, D1 = A0;

    int p = p0;
    for (; p + 4 <= p1; p += 4) {
        // stage 1: 4 independent index loads (contiguous: 1-2 sectors per warp)
        int na = g_srcs[p],     nb = g_srcs[p + 1];
        int nc = g_srcs[p + 2], nd = g_srcs[p + 3];
        // stage 2: 4 independent logit loads + 4 independent h-row gathers
        float ea = g_el[na * 4 + hq] + er_h;
        float eb = g_el[nb * 4 + hq] + er_h;
        float ec = g_el[nc * 4 + hq] + er_h;
        float ed = g_el[nd * 4 + hq] + er_h;
        float4 ha = ((const float4*)g_h)[na * 32 + lane];
        float4 hb = ((const float4*)g_h)[nb * 32 + lane];
        float4 hc = ((const float4*)g_h)[nc * 32 + lane];
        float4 hd = ((const float4*)g_h)[nd * 32 + lane];
        ea = (ea > 0.f) ? ea : NEG * ea;
        eb = (eb > 0.f) ? eb : NEG * eb;
        ec = (ec > 0.f) ? ec : NEG * ec;
        ed = (ed > 0.f) ? ed : NEG * ed;
        float xa = __expf(fminf(ea, 80.f)), xb = __expf(fminf(eb, 80.f));
        float xc = __expf(fminf(ec, 80.f)), xd = __expf(fminf(ed, 80.f));
        s_acc += (xa + xb) + (xc + xd);
        float2 da = dup(xa), db = dup(xb), dc = dup(xc), dd = dup(xd);
        ffma2(A0, make_float2(ha.x, ha.y), da); ffma2(A1, make_float2(ha.z, ha.w), da);
        ffma2(B0, make_float2(hb.x, hb.y), db); ffma2(B1, make_float2(hb.z, hb.w), db);
        ffma2(C0, make_float2(hc.x, hc.y), dc); ffma2(C1, make_float2(hc.z, hc.w), dc);
        ffma2(D0, make_float2(hd.x, hd.y), dd); ffma2(D1, make_float2(hd.z, hd.w), dd);
    }
    for (; p < p1; p++) {
        int na = g_srcs[p];
        float ea = g_el[na * 4 + hq] + er_h;
        float4 ha = ((const float4*)g_h)[na * 32 + lane];
        ea = (ea > 0.f) ? ea : NEG * ea;
        float xa = __expf(fminf(ea, 80.f));
        s_acc += xa;
        float2 da = dup(xa);
        ffma2(A0, make_float2(ha.x, ha.y), da);
        ffma2(A1, make_float2(ha.z, ha.w), da);
    }

    float inv = (s_acc > 0.f) ? (1.f / s_acc) : 0.f;
    float a0 = ((A0.x + B0.x) + (C0.x + D0.x)) * inv;
    float a1 = ((A0.y + B0.y) + (C0.y + D0.y)) * inv;
    float a2 = ((A1.x + B1.x) + (C1.x + D1.x)) * inv;
    float a3 = ((A1.y + B1.y) + (C1.y + D1.y)) * inv;

    if (!layer2) {
        float4 b = ((const float4*)bias)[lane];
        a0 = fmaxf(a0 + b.x, 0.f); a1 = fmaxf(a1 + b.y, 0.f);
        a2 = fmaxf(a2 + b.z, 0.f); a3 = fmaxf(a3 + b.w, 0.f);
        ((float4*)g_x2)[d * 32 + lane] = make_float4(a0, a1, a2, a3);
    } else {
        float4 b = ((const float4*)bias)[lane];
        a0 += b.x; a1 += b.y; a2 += b.z; a3 += b.w;
        // mean over heads: lanes {l, l+8, l+16, l+24} hold the 4 heads of out idx
        a0 += __shfl_xor_sync(0xffffffffu, a0, 8);  a0 += __shfl_xor_sync(0xffffffffu, a0, 16);
        a1 += __shfl_xor_sync(0xffffffffu, a1, 8);  a1 += __shfl_xor_sync(0xffffffffu, a1, 16);
        a2 += __shfl_xor_sync(0xffffffffu, a2, 8);  a2 += __shfl_xor_sync(0xffffffffu, a2, 16);
        a3 += __shfl_xor_sync(0xffffffffu, a3, 8);  a3 += __shfl_xor_sync(0xffffffffu, a3, 16);
        if (lane < 8)
            ((float4*)outExt)[d * 8 + lane] =
                make_float4(0.25f * a0, 0.25f * a1, 0.25f * a2, 0.25f * a3);
    }
}

// ---------------- launch ----------------
extern "C" void kernel_launch(void* const* d_in, const int* in_sizes, int n_in,
                              void* d_out, int out_size)
{
    const float* feat = (const float*)d_in[0];
    const int*   src  = (const int*)  d_in[1];
    const int*   dst  = (const int*)  d_in[2];
    const float* W1   = (const float*)d_in[3];
    const float* al1  = (const float*)d_in[4];
    const float* ar1  = (const float*)d_in[5];
    const float* b1   = (const float*)d_in[6];
    const float* W2   = (const float*)d_in[7];
    const float* al2  = (const float*)d_in[8];
    const float* ar2  = (const float*)d_in[9];
    const float* b2   = (const float*)d_in[10];
    float* out = (float*)d_out;

    // compact CSR build (graph shared by both layers)
    k_zero <<<(NN + 255) / 256, 256>>>();
    k_count<<<(EE + 255) / 256, 256>>>(dst);
    k_off  <<<(NN + 255) / 256, 256>>>();
    k_fill <<<(EE + 255) / 256, 256>>>(src, dst);

    // layer 1
    k_gemm<<<(NN + 31) / 32, 256>>>(feat, 1, W1, al1, ar1);
    k_agg <<<(NN * 32 + 255) / 256, 256>>>(b1, nullptr, 0);

    // layer 2
    k_gemm<<<(NN + 31) / 32, 256>>>(nullptr, 0, W2, al2, ar2);
    k_agg <<<(NN * 32 + 255) / 256, 256>>>(b2, out, 1);
}

// round 10
// speedup vs baseline: 1.0987x; 1.0987x over previous
#include <cuda_runtime.h>

#define NN 100000
#define EE 800000
#define NEG 0.2f

// ---------------- scratch (device globals; no allocation allowed) ----------------
__device__ __align__(16) float g_h [NN * 128];   // projected features (both layers)
__device__ __align__(16) float g_x2[NN * 128];   // layer-1 output / layer-2 input
__device__ __align__(16) float g_el[NN * 4];
__device__ __align__(16) float g_er[NN * 4];
__device__ int g_deg [NN];
__device__ int g_off [NN];
__device__ int g_cur [NN];
__device__ int g_srcs[EE];                       // src node per CSR slot (dense: 3.2MB)
__device__ int g_tot;

// packed f32x2 FMA: 2 FMAs per issue slot (FFMA2) — PTX-only path
__device__ __forceinline__ void ffma2(float2& d, float2 a, float2 b) {
    asm("fma.rn.f32x2 %0, %1, %2, %0;"
        : "+l"(reinterpret_cast<unsigned long long&>(d))
        : "l"(reinterpret_cast<const unsigned long long&>(a)),
          "l"(reinterpret_cast<const unsigned long long&>(b)));
}
__device__ __forceinline__ float2 dup(float x) { return make_float2(x, x); }

// ---------------- CSR build (scan-free, compact) ----------------
__global__ void k_zero() {
    int i = blockIdx.x * blockDim.x + threadIdx.x;
    if (i < NN) g_deg[i] = 0;
    if (i == 0) g_tot = 0;
}

__global__ void k_count(const int* __restrict__ dst) {
    int e = blockIdx.x * blockDim.x + threadIdx.x;
    if (e < EE) atomicAdd(&g_deg[dst[e]], 1);
}

// warp-level exclusive scan + one global atomic per warp; CSR segment ORDER is
// arbitrary (only per-dst grouping matters), so no global scan needed.
__global__ void k_off() {
    int i = blockIdx.x * blockDim.x + threadIdx.x;
    int lane = threadIdx.x & 31;
    int v = (i < NN) ? g_deg[i] : 0;
    int x = v;
    #pragma unroll
    for (int o = 1; o < 32; o <<= 1) {
        int t = __shfl_up_sync(0xffffffffu, x, o);
        if (lane >= o) x += t;
    }
    int excl = x - v;
    int wsum = __shfl_sync(0xffffffffu, x, 31);
    int base = 0;
    if (lane == 31) base = atomicAdd(&g_tot, wsum);
    base = __shfl_sync(0xffffffffu, base, 31);
    if (i < NN) {
        g_off[i] = base + excl;
        g_cur[i] = base + excl;
    }
}

__global__ void k_fill(const int* __restrict__ src, const int* __restrict__ dst) {
    int e = blockIdx.x * blockDim.x + threadIdx.x;
    if (e < EE) {
        int p = atomicAdd(&g_cur[dst[e]], 1);
        g_srcs[p] = src[e];
    }
}
// after k_fill: g_off = start, g_cur = end of each node's CSR segment

// ---------------- GEMM + attention-logit epilogue (FFMA2 core) ----------------
// Block = 256 threads (8 warps), each warp computes 4 nodes x 128 cols.
// At the fp32 FMA-issue roofline (~49us per GEMM).
__global__ void k_gemm(const float* __restrict__ Xext, int useExt,
                       const float* __restrict__ W,
                       const float* __restrict__ al, const float* __restrict__ ar)
{
    __shared__ float4 xs[8][128];  // per-warp: 4 nodes' x packed per k
    const float* X = useExt ? Xext : g_x2;
    int w = threadIdx.x >> 5, lane = threadIdx.x & 31;
    int n0 = blockIdx.x * 32 + w * 4;

    float* xsf = (float*)&xs[w][0];
    #pragma unroll
    for (int r = 0; r < 4; r++) {
        int n = n0 + r;
        const float* xr = X + (long)n * 128;
        #pragma unroll
        for (int i = 0; i < 4; i++) {
            int c = lane + 32 * i;
            xsf[c * 4 + r] = (n < NN) ? xr[c] : 0.f;
        }
    }
    __syncwarp();

    float2 acc[4][2];  // [col][rowpair]
    #pragma unroll
    for (int c = 0; c < 4; c++) {
        acc[c][0] = make_float2(0.f, 0.f);
        acc[c][1] = make_float2(0.f, 0.f);
    }

    const float4* Wv = (const float4*)W;
    #pragma unroll 4
    for (int k = 0; k < 128; k++) {
        float4 wv = Wv[k * 32 + lane];
        float4 xk = xs[w][k];
        float2 x01 = make_float2(xk.x, xk.y);
        float2 x23 = make_float2(xk.z, xk.w);
        float2 w0 = dup(wv.x), w1 = dup(wv.y), w2 = dup(wv.z), w3 = dup(wv.w);
        ffma2(acc[0][0], x01, w0); ffma2(acc[0][1], x23, w0);
        ffma2(acc[1][0], x01, w1); ffma2(acc[1][1], x23, w1);
        ffma2(acc[2][0], x01, w2); ffma2(acc[2][1], x23, w2);
        ffma2(acc[3][0], x01, w3); ffma2(acc[3][1], x23, w3);
    }

    float av[4][4];
    #pragma unroll
    for (int c = 0; c < 4; c++) {
        av[0][c] = acc[c][0].x; av[1][c] = acc[c][0].y;
        av[2][c] = acc[c][1].x; av[3][c] = acc[c][1].y;
    }

    // epilogue: store h, and el/er = per-head dot(h, attn) via 8-lane reductions.
    float4 al4 = ((const float4*)al)[lane];
    float4 ar4 = ((const float4*)ar)[lane];
    int head = lane >> 3;
    #pragma unroll
    for (int r = 0; r < 4; r++) {
        int n = n0 + r;
        float pel = av[r][0]*al4.x + av[r][1]*al4.y + av[r][2]*al4.z + av[r][3]*al4.w;
        float per = av[r][0]*ar4.x + av[r][1]*ar4.y + av[r][2]*ar4.z + av[r][3]*ar4.w;
        #pragma unroll
        for (int o = 1; o < 8; o <<= 1) {
            pel += __shfl_xor_sync(0xffffffffu, pel, o);
            per += __shfl_xor_sync(0xffffffffu, per, o);
        }
        if (n < NN) {
            ((float4*)g_h)[n * 32 + lane] = make_float4(av[r][0], av[r][1], av[r][2], av[r][3]);
            if ((lane & 7) == 0) {
                g_el[n * 4 + head] = pel;
                g_er[n * 4 + head] = per;
            }
        }
    }
}

// ---------------- fused softmax + aggregation, single pass ----------------
// R3 structure (2-wide, no launch bounds) + cross-iteration index prefetch:
// the next pair's src indices are loaded while the current pair's el/h loads
// are in flight, breaking the idx->data dependent L2 chain.
// Normalization deferred: out = (sum ex*h)/(sum ex). No max-subtraction
// (logits O(1)-scale; fminf(.,80) guard is a no-op; softmax shift-invariant).
__global__ void k_agg(const float* __restrict__ bias, float* __restrict__ outExt, int layer2)
{
    int d    = (blockIdx.x * blockDim.x + threadIdx.x) >> 5;
    int lane = threadIdx.x & 31;
    if (d >= NN) return;
    int hq = lane >> 3;
    int p0 = g_off[d], p1 = g_cur[d];

    float er_h = g_er[d * 4 + hq];

    float sA = 0.f, sB = 0.f;
    float2 A0 = make_float2(0.f, 0.f), A1 = A0, B0 = A0, B1 = A0;

    int p = p0;
    int na = 0, nb = 0;
    if (p + 2 <= p1) { na = g_srcs[p]; nb = g_srcs[p + 1]; }
    while (p + 2 <= p1) {
        int np = p + 2;
        int nna = 0, nnb = 0;
        if (np + 2 <= p1) { nna = g_srcs[np]; nnb = g_srcs[np + 1]; }  // prefetch next pair
        float eA = g_el[na * 4 + hq] + er_h;
        float eB = g_el[nb * 4 + hq] + er_h;
        float4 hA = ((const float4*)g_h)[na * 32 + lane];
        float4 hB = ((const float4*)g_h)[nb * 32 + lane];
        eA = (eA > 0.f) ? eA : NEG * eA;
        eB = (eB > 0.f) ? eB : NEG * eB;
        float xA = __expf(fminf(eA, 80.f));
        float xB = __expf(fminf(eB, 80.f));
        sA += xA; sB += xB;
        float2 dA = dup(xA), dB = dup(xB);
        ffma2(A0, make_float2(hA.x, hA.y), dA);
        ffma2(A1, make_float2(hA.z, hA.w), dA);
        ffma2(B0, make_float2(hB.x, hB.y), dB);
        ffma2(B1, make_float2(hB.z, hB.w), dB);
        na = nna; nb = nnb; p = np;
    }
    if (p < p1) {
        int nc = g_srcs[p];
        float eA = g_el[nc * 4 + hq] + er_h;
        float4 hA = ((const float4*)g_h)[nc * 32 + lane];
        eA = (eA > 0.f) ? eA : NEG * eA;
        float xA = __expf(fminf(eA, 80.f));
        sA += xA;
        float2 dA = dup(xA);
        ffma2(A0, make_float2(hA.x, hA.y), dA);
        ffma2(A1, make_float2(hA.z, hA.w), dA);
    }

    float s = sA + sB;
    float inv = (s > 0.f) ? (1.f / s) : 0.f;
    float a0 = (A0.x + B0.x) * inv;
    float a1 = (A0.y + B0.y) * inv;
    float a2 = (A1.x + B1.x) * inv;
    float a3 = (A1.y + B1.y) * inv;

    if (!layer2) {
        float4 b = ((const float4*)bias)[lane];
        a0 = fmaxf(a0 + b.x, 0.f); a1 = fmaxf(a1 + b.y, 0.f);
        a2 = fmaxf(a2 + b.z, 0.f); a3 = fmaxf(a3 + b.w, 0.f);
        ((float4*)g_x2)[d * 32 + lane] = make_float4(a0, a1, a2, a3);
    } else {
        float4 b = ((const float4*)bias)[lane];
        a0 += b.x; a1 += b.y; a2 += b.z; a3 += b.w;
        // mean over heads: lanes {l, l+8, l+16, l+24} hold the 4 heads of out idx
        a0 += __shfl_xor_sync(0xffffffffu, a0, 8);  a0 += __shfl_xor_sync(0xffffffffu, a0, 16);
        a1 += __shfl_xor_sync(0xffffffffu, a1, 8);  a1 += __shfl_xor_sync(0xffffffffu, a1, 16);
        a2 += __shfl_xor_sync(0xffffffffu, a2, 8);  a2 += __shfl_xor_sync(0xffffffffu, a2, 16);
        a3 += __shfl_xor_sync(0xffffffffu, a3, 8);  a3 += __shfl_xor_sync(0xffffffffu, a3, 16);
        if (lane < 8)
            ((float4*)outExt)[d * 8 + lane] =
                make_float4(0.25f * a0, 0.25f * a1, 0.25f * a2, 0.25f * a3);
    }
}

// ---------------- launch ----------------
extern "C" void kernel_launch(void* const* d_in, const int* in_sizes, int n_in,
                              void* d_out, int out_size)
{
    const float* feat = (const float*)d_in[0];
    const int*   src  = (const int*)  d_in[1];
    const int*   dst  = (const int*)  d_in[2];
    const float* W1   = (const float*)d_in[3];
    const float* al1  = (const float*)d_in[4];
    const float* ar1  = (const float*)d_in[5];
    const float* b1   = (const float*)d_in[6];
    const float* W2   = (const float*)d_in[7];
    const float* al2  = (const float*)d_in[8];
    const float* ar2  = (const float*)d_in[9];
    const float* b2   = (const float*)d_in[10];
    float* out = (float*)d_out;

    // compact CSR build (graph shared by both layers)
    k_zero <<<(NN + 255) / 256, 256>>>();
    k_count<<<(EE + 255) / 256, 256>>>(dst);
    k_off  <<<(NN + 255) / 256, 256>>>();
    k_fill <<<(EE + 255) / 256, 256>>>(src, dst);

    // layer 1
    k_gemm<<<(NN + 31) / 32, 256>>>(feat, 1, W1, al1, ar1);
    k_agg <<<(NN * 32 + 255) / 256, 256>>>(b1, nullptr, 0);

    // layer 2
    k_gemm<<<(NN + 31) / 32, 256>>>(nullptr, 0, W2, al2, ar2);
    k_agg <<<(NN * 32 + 255) / 256, 256>>>(b2, out, 1);
}

// round 11
// speedup vs baseline: 1.2401x; 1.1287x over previous
#include <cuda_runtime.h>
#include <cuda_bf16.h>

#define NN 100000
#define EE 800000
#define NEG 0.2f

#define LDA 136          // padded row stride (bf16) for A/W smem tiles
#define LDC 132          // padded row stride (f32) for C staging
#define W_TILE_BYTES (128 * LDA * 2)          // 34816
#define AW_BYTES     (2 * 16 * LDA * 2)       // 8704 per warp (hi+lo)
#define SMEM_TOTAL   (2 * W_TILE_BYTES + 8 * AW_BYTES)   // 139264

// ---------------- scratch (device globals; no allocation allowed) ----------------
__device__ __align__(16) float g_h [NN * 128];
__device__ __align__(16) float g_x2[NN * 128];
__device__ __align__(16) float g_el[NN * 4];
__device__ __align__(16) float g_er[NN * 4];
__device__ int g_deg [NN];
__device__ int g_off [NN];
__device__ int g_cur [NN];
__device__ int g_srcs[EE];
__device__ int g_tot;
__device__ __align__(4) __nv_bfloat16 g_wthi[2 * 16384];  // Wt hi, [layer][n][k]
__device__ __align__(4) __nv_bfloat16 g_wtlo[2 * 16384];  // Wt lo

// packed f32x2 FMA (agg kernel)
__device__ __forceinline__ void ffma2(float2& d, float2 a, float2 b) {
    asm("fma.rn.f32x2 %0, %1, %2, %0;"
        : "+l"(reinterpret_cast<unsigned long long&>(d))
        : "l"(reinterpret_cast<const unsigned long long&>(a)),
          "l"(reinterpret_cast<const unsigned long long&>(b)));
}
__device__ __forceinline__ float2 dup(float x) { return make_float2(x, x); }

// bf16 hi/lo split of a float2, packed as 2x uint32 (bf16x2)
__device__ __forceinline__ void bf16split(float2 v, unsigned& hi, unsigned& lo) {
    __nv_bfloat162 h = __float22bfloat162_rn(v);
    float2 hf = __bfloat1622float2(h);
    __nv_bfloat162 l = __float22bfloat162_rn(make_float2(v.x - hf.x, v.y - hf.y));
    hi = *reinterpret_cast<unsigned*>(&h);
    lo = *reinterpret_cast<unsigned*>(&l);
}

__device__ __forceinline__ void mma16816(float* c, const unsigned* a, unsigned b0, unsigned b1) {
    asm volatile(
        "mma.sync.aligned.m16n8k16.row.col.f32.bf16.bf16.f32 "
        "{%0,%1,%2,%3},{%4,%5,%6,%7},{%8,%9},{%0,%1,%2,%3};"
        : "+f"(c[0]), "+f"(c[1]), "+f"(c[2]), "+f"(c[3])
        : "r"(a[0]), "r"(a[1]), "r"(a[2]), "r"(a[3]), "r"(b0), "r"(b1));
}

// ---------------- CSR build (scan-free, compact) ----------------
__global__ void k_zero() {
    int i = blockIdx.x * blockDim.x + threadIdx.x;
    if (i < NN) g_deg[i] = 0;
    if (i == 0) g_tot = 0;
}

__global__ void k_count(const int* __restrict__ dst) {
    int e = blockIdx.x * blockDim.x + threadIdx.x;
    if (e < EE) atomicAdd(&g_deg[dst[e]], 1);
}

__global__ void k_off() {
    int i = blockIdx.x * blockDim.x + threadIdx.x;
    int lane = threadIdx.x & 31;
    int v = (i < NN) ? g_deg[i] : 0;
    int x = v;
    #pragma unroll
    for (int o = 1; o < 32; o <<= 1) {
        int t = __shfl_up_sync(0xffffffffu, x, o);
        if (lane >= o) x += t;
    }
    int excl = x - v;
    int wsum = __shfl_sync(0xffffffffu, x, 31);
    int base = 0;
    if (lane == 31) base = atomicAdd(&g_tot, wsum);
    base = __shfl_sync(0xffffffffu, base, 31);
    if (i < NN) {
        g_off[i] = base + excl;
        g_cur[i] = base + excl;
    }
}

__global__ void k_fill(const int* __restrict__ src, const int* __restrict__ dst) {
    int e = blockIdx.x * blockDim.x + threadIdx.x;
    if (e < EE) {
        int p = atomicAdd(&g_cur[dst[e]], 1);
        g_srcs[p] = src[e];
    }
}

// ---------------- W prep: transpose + bf16 hi/lo split, both layers ----------------
__global__ void k_wprep(const float* __restrict__ W1, const float* __restrict__ W2) {
    int i = blockIdx.x * 256 + threadIdx.x;
    if (i < 32768) {
        int l = i >> 14, j = i & 16383;
        int n = j >> 7, k = j & 127;
        float x = (l ? W2 : W1)[k * 128 + n];
        __nv_bfloat16 h = __float2bfloat16_rn(x);
        g_wthi[i] = h;
        g_wtlo[i] = __float2bfloat16_rn(x - __bfloat162float(h));
    }
}

// ---------------- tensor-core GEMM + attention-logit epilogue --------------------
// Block: 256 thr / 8 warps / 128 nodes. Warp: 16 nodes x 128 cols via
// m16n8k16 bf16 mma, 3-term split (xh*Wh + xh*Wl + xl*Wh), fp32 accum.
// SMEM: Wt hi/lo [128][LDA] shared; per-warp A hi/lo [16][LDA] (reused as C).
__global__ void k_gemm_tc(const float* __restrict__ Xext, int useExt, int layer,
                          const float* __restrict__ al, const float* __restrict__ ar)
{
    extern __shared__ char sm[];
    __nv_bfloat16* Whi = (__nv_bfloat16*)sm;
    __nv_bfloat16* Wlo = Whi + 128 * LDA;
    const float* X = useExt ? Xext : g_x2;

    int tid = threadIdx.x;
    int w = tid >> 5, lane = tid & 31;
    char* abase = sm + 2 * W_TILE_BYTES + w * AW_BYTES;
    __nv_bfloat16* Ahi = (__nv_bfloat16*)abase;
    __nv_bfloat16* Alo = Ahi + 16 * LDA;
    float* Cst = (float*)abase;

    // stage W (transposed, pre-split) into padded smem
    const __nv_bfloat16* gwh = g_wthi + layer * 16384;
    const __nv_bfloat16* gwl = g_wtlo + layer * 16384;
    for (int i = tid; i < 16384; i += 256) {
        int n = i >> 7, k = i & 127;
        Whi[n * LDA + k] = gwh[i];
        Wlo[n * LDA + k] = gwl[i];
    }

    // stage this warp's 16 node rows, split to bf16 hi/lo
    int nb = blockIdx.x * 128 + w * 16;
    #pragma unroll 4
    for (int r = 0; r < 16; r++) {
        int n = nb + r;
        float4 v = (n < NN) ? ((const float4*)X)[n * 32 + lane]
                            : make_float4(0.f, 0.f, 0.f, 0.f);
        unsigned h01, l01, h23, l23;
        bf16split(make_float2(v.x, v.y), h01, l01);
        bf16split(make_float2(v.z, v.w), h23, l23);
        *(unsigned*)&Ahi[r * LDA + lane * 4]     = h01;
        *(unsigned*)&Ahi[r * LDA + lane * 4 + 2] = h23;
        *(unsigned*)&Alo[r * LDA + lane * 4]     = l01;
        *(unsigned*)&Alo[r * LDA + lane * 4 + 2] = l23;
    }
    __syncthreads();

    // mainloop
    float c[16][4];
    #pragma unroll
    for (int nt = 0; nt < 16; nt++)
        c[nt][0] = c[nt][1] = c[nt][2] = c[nt][3] = 0.f;

    int g = lane >> 2, tg2 = (lane & 3) * 2;
    #pragma unroll
    for (int ks = 0; ks < 8; ks++) {
        int kc = ks * 16;
        unsigned ah[4], alr[4];
        ah[0]  = *(unsigned*)&Ahi[ g      * LDA + kc     + tg2];
        ah[1]  = *(unsigned*)&Ahi[(g + 8) * LDA + kc     + tg2];
        ah[2]  = *(unsigned*)&Ahi[ g      * LDA + kc + 8 + tg2];
        ah[3]  = *(unsigned*)&Ahi[(g + 8) * LDA + kc + 8 + tg2];
        alr[0] = *(unsigned*)&Alo[ g      * LDA + kc     + tg2];
        alr[1] = *(unsigned*)&Alo[(g + 8) * LDA + kc     + tg2];
        alr[2] = *(unsigned*)&Alo[ g      * LDA + kc + 8 + tg2];
        alr[3] = *(unsigned*)&Alo[(g + 8) * LDA + kc + 8 + tg2];
        #pragma unroll
        for (int nt = 0; nt < 16; nt++) {
            int n = nt * 8 + g;
            unsigned bh0 = *(unsigned*)&Whi[n * LDA + kc     + tg2];
            unsigned bh1 = *(unsigned*)&Whi[n * LDA + kc + 8 + tg2];
            unsigned bl0 = *(unsigned*)&Wlo[n * LDA + kc     + tg2];
            unsigned bl1 = *(unsigned*)&Wlo[n * LDA + kc + 8 + tg2];
            mma16816(c[nt], ah,  bh0, bh1);
            mma16816(c[nt], ah,  bl0, bl1);
            mma16816(c[nt], alr, bh0, bh1);
        }
    }

    // stage C to smem (A region done being read by this warp), then epilogue
    __syncwarp();
    #pragma unroll
    for (int nt = 0; nt < 16; nt++) {
        int ncol = nt * 8 + tg2;
        Cst[ g      * LDC + ncol]     = c[nt][0];
        Cst[ g      * LDC + ncol + 1] = c[nt][1];
        Cst[(g + 8) * LDC + ncol]     = c[nt][2];
        Cst[(g + 8) * LDC + ncol + 1] = c[nt][3];
    }
    __syncwarp();

    float4 al4 = ((const float4*)al)[lane];
    float4 ar4 = ((const float4*)ar)[lane];
    int head = lane >> 3;
    #pragma unroll 4
    for (int r = 0; r < 16; r++) {
        int n = nb + r;
        if (n >= NN) break;
        float4 hv = *(float4*)&Cst[r * LDC + lane * 4];
        float pel = hv.x * al4.x + hv.y * al4.y + hv.z * al4.z + hv.w * al4.w;
        float per = hv.x * ar4.x + hv.y * ar4.y + hv.z * ar4.z + hv.w * ar4.w;
        #pragma unroll
        for (int o = 1; o < 8; o <<= 1) {
            pel += __shfl_xor_sync(0xffffffffu, pel, o);
            per += __shfl_xor_sync(0xffffffffu, per, o);
        }
        ((float4*)g_h)[n * 32 + lane] = hv;
        if ((lane & 7) == 0) {
            g_el[n * 4 + head] = pel;
            g_er[n * 4 + head] = per;
        }
    }
}

// ---------------- fused softmax + aggregation (R10 best, unchanged) --------------
__global__ void k_agg(const float* __restrict__ bias, float* __restrict__ outExt, int layer2)
{
    int d    = (blockIdx.x * blockDim.x + threadIdx.x) >> 5;
    int lane = threadIdx.x & 31;
    if (d >= NN) return;
    int hq = lane >> 3;
    int p0 = g_off[d], p1 = g_cur[d];

    float er_h = g_er[d * 4 + hq];

    float sA = 0.f, sB = 0.f;
    float2 A0 = make_float2(0.f, 0.f), A1 = A0, B0 = A0, B1 = A0;

    int p = p0;
    int na = 0, nb = 0;
    if (p + 2 <= p1) { na = g_srcs[p]; nb = g_srcs[p + 1]; }
    while (p + 2 <= p1) {
        int np = p + 2;
        int nna = 0, nnb = 0;
        if (np + 2 <= p1) { nna = g_srcs[np]; nnb = g_srcs[np + 1]; }
        float eA = g_el[na * 4 + hq] + er_h;
        float eB = g_el[nb * 4 + hq] + er_h;
        float4 hA = ((const float4*)g_h)[na * 32 + lane];
        float4 hB = ((const float4*)g_h)[nb * 32 + lane];
        eA = (eA > 0.f) ? eA : NEG * eA;
        eB = (eB > 0.f) ? eB : NEG * eB;
        float xA = __expf(fminf(eA, 80.f));
        float xB = __expf(fminf(eB, 80.f));
        sA += xA; sB += xB;
        float2 dA = dup(xA), dB = dup(xB);
        ffma2(A0, make_float2(hA.x, hA.y), dA);
        ffma2(A1, make_float2(hA.z, hA.w), dA);
        ffma2(B0, make_float2(hB.x, hB.y), dB);
        ffma2(B1, make_float2(hB.z, hB.w), dB);
        na = nna; nb = nnb; p = np;
    }
    if (p < p1) {
        int nc = g_srcs[p];
        float eA = g_el[nc * 4 + hq] + er_h;
        float4 hA = ((const float4*)g_h)[nc * 32 + lane];
        eA = (eA > 0.f) ? eA : NEG * eA;
        float xA = __expf(fminf(eA, 80.f));
        sA += xA;
        float2 dA = dup(xA);
        ffma2(A0, make_float2(hA.x, hA.y), dA);
        ffma2(A1, make_float2(hA.z, hA.w), dA);
    }

    float s = sA + sB;
    float inv = (s > 0.f) ? (1.f / s) : 0.f;
    float a0 = (A0.x + B0.x) * inv;
    float a1 = (A0.y + B0.y) * inv;
    float a2 = (A1.x + B1.x) * inv;
    float a3 = (A1.y + B1.y) * inv;

    if (!layer2) {
        float4 b = ((const float4*)bias)[lane];
        a0 = fmaxf(a0 + b.x, 0.f); a1 = fmaxf(a1 + b.y, 0.f);
        a2 = fmaxf(a2 + b.z, 0.f); a3 = fmaxf(a3 + b.w, 0.f);
        ((float4*)g_x2)[d * 32 + lane] = make_float4(a0, a1, a2, a3);
    } else {
        float4 b = ((const float4*)bias)[lane];
        a0 += b.x; a1 += b.y; a2 += b.z; a3 += b.w;
        a0 += __shfl_xor_sync(0xffffffffu, a0, 8);  a0 += __shfl_xor_sync(0xffffffffu, a0, 16);
        a1 += __shfl_xor_sync(0xffffffffu, a1, 8);  a1 += __shfl_xor_sync(0xffffffffu, a1, 16);
        a2 += __shfl_xor_sync(0xffffffffu, a2, 8);  a2 += __shfl_xor_sync(0xffffffffu, a2, 16);
        a3 += __shfl_xor_sync(0xffffffffu, a3, 8);  a3 += __shfl_xor_sync(0xffffffffu, a3, 16);
        if (lane < 8)
            ((float4*)outExt)[d * 8 + lane] =
                make_float4(0.25f * a0, 0.25f * a1, 0.25f * a2, 0.25f * a3);
    }
}

// ---------------- launch ----------------
extern "C" void kernel_launch(void* const* d_in, const int* in_sizes, int n_in,
                              void* d_out, int out_size)
{
    const float* feat = (const float*)d_in[0];
    const int*   src  = (const int*)  d_in[1];
    const int*   dst  = (const int*)  d_in[2];
    const float* W1   = (const float*)d_in[3];
    const float* al1  = (const float*)d_in[4];
    const float* ar1  = (const float*)d_in[5];
    const float* b1   = (const float*)d_in[6];
    const float* W2   = (const float*)d_in[7];
    const float* al2  = (const float*)d_in[8];
    const float* ar2  = (const float*)d_in[9];
    const float* b2   = (const float*)d_in[10];
    float* out = (float*)d_out;

    cudaFuncSetAttribute(k_gemm_tc, cudaFuncAttributeMaxDynamicSharedMemorySize, SMEM_TOTAL);

    // CSR build + W prep (graph/weights shared by both layers)
    k_zero <<<(NN + 255) / 256, 256>>>();
    k_count<<<(EE + 255) / 256, 256>>>(dst);
    k_off  <<<(NN + 255) / 256, 256>>>();
    k_fill <<<(EE + 255) / 256, 256>>>(src, dst);
    k_wprep<<<128, 256>>>(W1, W2);

    int gblocks = (NN + 127) / 128;
    // layer 1
    k_gemm_tc<<<gblocks, 256, SMEM_TOTAL>>>(feat, 1, 0, al1, ar1);
    k_agg <<<(NN * 32 + 255) / 256, 256>>>(b1, nullptr, 0);

    // layer 2
    k_gemm_tc<<<gblocks, 256, SMEM_TOTAL>>>(nullptr, 0, 1, al2, ar2);
    k_agg <<<(NN * 32 + 255) / 256, 256>>>(b2, out, 1);
}

// round 12
// speedup vs baseline: 1.2697x; 1.0239x over previous
#include <cuda_runtime.h>
#include <cuda_bf16.h>

#define NN 100000
#define EE 800000
#define NEG 0.2f

#define LDA 136          // padded row stride (bf16) for A/W smem tiles
#define LDC 132          // padded row stride (f32) for C staging
#define W_TILE_BYTES (128 * LDA * 2)          // 34816
#define AW_BYTES     (2 * 16 * LDA * 2)       // 8704 per warp (hi+lo)
#define SMEM_TOTAL   (2 * W_TILE_BYTES + 8 * AW_BYTES)   // 139264

// ---------------- scratch (device globals; no allocation allowed) ----------------
__device__ __align__(16) float g_h [NN * 128];
__device__ __align__(16) float g_x2[NN * 128];
__device__ __align__(16) float g_el[NN * 4];
__device__ __align__(16) float g_er[NN * 4];
__device__ int g_deg [NN];
__device__ int g_off [NN];
__device__ int g_cur [NN];
__device__ int g_srcs[EE];
__device__ int g_tot;
__device__ __align__(4) __nv_bfloat16 g_wthi[2 * 16384];  // Wt hi, [layer][n][k]
__device__ __align__(4) __nv_bfloat16 g_wtlo[2 * 16384];  // Wt lo

// packed f32x2 FMA (agg kernel)
__device__ __forceinline__ void ffma2(float2& d, float2 a, float2 b) {
    asm("fma.rn.f32x2 %0, %1, %2, %0;"
        : "+l"(reinterpret_cast<unsigned long long&>(d))
        : "l"(reinterpret_cast<const unsigned long long&>(a)),
          "l"(reinterpret_cast<const unsigned long long&>(b)));
}
__device__ __forceinline__ float2 dup(float x) { return make_float2(x, x); }

// bf16 hi/lo split of a float2, packed as 2x uint32 (bf16x2)
__device__ __forceinline__ void bf16split(float2 v, unsigned& hi, unsigned& lo) {
    __nv_bfloat162 h = __float22bfloat162_rn(v);
    float2 hf = __bfloat1622float2(h);
    __nv_bfloat162 l = __float22bfloat162_rn(make_float2(v.x - hf.x, v.y - hf.y));
    hi = *reinterpret_cast<unsigned*>(&h);
    lo = *reinterpret_cast<unsigned*>(&l);
}

__device__ __forceinline__ void mma16816(float* c, const unsigned* a, unsigned b0, unsigned b1) {
    asm volatile(
        "mma.sync.aligned.m16n8k16.row.col.f32.bf16.bf16.f32 "
        "{%0,%1,%2,%3},{%4,%5,%6,%7},{%8,%9},{%0,%1,%2,%3};"
        : "+f"(c[0]), "+f"(c[1]), "+f"(c[2]), "+f"(c[3])
        : "r"(a[0]), "r"(a[1]), "r"(a[2]), "r"(a[3]), "r"(b0), "r"(b1));
}

// ---------------- CSR build (scan-free, compact; int4-vectorized) ----------------
__global__ void k_zero() {
    int i = blockIdx.x * blockDim.x + threadIdx.x;
    if (i < NN) g_deg[i] = 0;
    if (i == 0) g_tot = 0;
}

__global__ void k_count(const int* __restrict__ dst) {
    int e = blockIdx.x * blockDim.x + threadIdx.x;   // e indexes int4 groups
    if (e < EE / 4) {
        int4 d4 = ((const int4*)dst)[e];
        atomicAdd(&g_deg[d4.x], 1);
        atomicAdd(&g_deg[d4.y], 1);
        atomicAdd(&g_deg[d4.z], 1);
        atomicAdd(&g_deg[d4.w], 1);
    }
}

__global__ void k_off() {
    int i = blockIdx.x * blockDim.x + threadIdx.x;
    int lane = threadIdx.x & 31;
    int v = (i < NN) ? g_deg[i] : 0;
    int x = v;
    #pragma unroll
    for (int o = 1; o < 32; o <<= 1) {
        int t = __shfl_up_sync(0xffffffffu, x, o);
        if (lane >= o) x += t;
    }
    int excl = x - v;
    int wsum = __shfl_sync(0xffffffffu, x, 31);
    int base = 0;
    if (lane == 31) base = atomicAdd(&g_tot, wsum);
    base = __shfl_sync(0xffffffffu, base, 31);
    if (i < NN) {
        g_off[i] = base + excl;
        g_cur[i] = base + excl;
    }
}

__global__ void k_fill(const int* __restrict__ src, const int* __restrict__ dst) {
    int e = blockIdx.x * blockDim.x + threadIdx.x;   // e indexes int4 groups
    if (e < EE / 4) {
        int4 d4 = ((const int4*)dst)[e];
        int4 s4 = ((const int4*)src)[e];
        g_srcs[atomicAdd(&g_cur[d4.x], 1)] = s4.x;
        g_srcs[atomicAdd(&g_cur[d4.y], 1)] = s4.y;
        g_srcs[atomicAdd(&g_cur[d4.z], 1)] = s4.z;
        g_srcs[atomicAdd(&g_cur[d4.w], 1)] = s4.w;
    }
}

// ---------------- W prep: transpose + bf16 hi/lo split, both layers ----------------
__global__ void k_wprep(const float* __restrict__ W1, const float* __restrict__ W2) {
    int i = blockIdx.x * 256 + threadIdx.x;
    if (i < 32768) {
        int l = i >> 14, j = i & 16383;
        int n = j >> 7, k = j & 127;
        float x = (l ? W2 : W1)[k * 128 + n];
        __nv_bfloat16 h = __float2bfloat16_rn(x);
        g_wthi[i] = h;
        g_wtlo[i] = __float2bfloat16_rn(x - __bfloat162float(h));
    }
}

// ---------------- tensor-core GEMM + attention-logit epilogue --------------------
__global__ void k_gemm_tc(const float* __restrict__ Xext, int useExt, int layer,
                          const float* __restrict__ al, const float* __restrict__ ar)
{
    extern __shared__ char sm[];
    __nv_bfloat16* Whi = (__nv_bfloat16*)sm;
    __nv_bfloat16* Wlo = Whi + 128 * LDA;
    const float* X = useExt ? Xext : g_x2;

    int tid = threadIdx.x;
    int w = tid >> 5, lane = tid & 31;
    char* abase = sm + 2 * W_TILE_BYTES + w * AW_BYTES;
    __nv_bfloat16* Ahi = (__nv_bfloat16*)abase;
    __nv_bfloat16* Alo = Ahi + 16 * LDA;
    float* Cst = (float*)abase;

    const __nv_bfloat16* gwh = g_wthi + layer * 16384;
    const __nv_bfloat16* gwl = g_wtlo + layer * 16384;
    for (int i = tid; i < 16384; i += 256) {
        int n = i >> 7, k = i & 127;
        Whi[n * LDA + k] = gwh[i];
        Wlo[n * LDA + k] = gwl[i];
    }

    int nb = blockIdx.x * 128 + w * 16;
    #pragma unroll 4
    for (int r = 0; r < 16; r++) {
        int n = nb + r;
        float4 v = (n < NN) ? ((const float4*)X)[n * 32 + lane]
                            : make_float4(0.f, 0.f, 0.f, 0.f);
        unsigned h01, l01, h23, l23;
        bf16split(make_float2(v.x, v.y), h01, l01);
        bf16split(make_float2(v.z, v.w), h23, l23);
        *(unsigned*)&Ahi[r * LDA + lane * 4]     = h01;
        *(unsigned*)&Ahi[r * LDA + lane * 4 + 2] = h23;
        *(unsigned*)&Alo[r * LDA + lane * 4]     = l01;
        *(unsigned*)&Alo[r * LDA + lane * 4 + 2] = l23;
    }
    __syncthreads();

    float c[16][4];
    #pragma unroll
    for (int nt = 0; nt < 16; nt++)
        c[nt][0] = c[nt][1] = c[nt][2] = c[nt][3] = 0.f;

    int g = lane >> 2, tg2 = (lane & 3) * 2;
    #pragma unroll
    for (int ks = 0; ks < 8; ks++) {
        int kc = ks * 16;
        unsigned ah[4], alr[4];
        ah[0]  = *(unsigned*)&Ahi[ g      * LDA + kc     + tg2];
        ah[1]  = *(unsigned*)&Ahi[(g + 8) * LDA + kc     + tg2];
        ah[2]  = *(unsigned*)&Ahi[ g      * LDA + kc + 8 + tg2];
        ah[3]  = *(unsigned*)&Ahi[(g + 8) * LDA + kc + 8 + tg2];
        alr[0] = *(unsigned*)&Alo[ g      * LDA + kc     + tg2];
        alr[1] = *(unsigned*)&Alo[(g + 8) * LDA + kc     + tg2];
        alr[2] = *(unsigned*)&Alo[ g      * LDA + kc + 8 + tg2];
        alr[3] = *(unsigned*)&Alo[(g + 8) * LDA + kc + 8 + tg2];
        #pragma unroll
        for (int nt = 0; nt < 16; nt++) {
            int n = nt * 8 + g;
            unsigned bh0 = *(unsigned*)&Whi[n * LDA + kc     + tg2];
            unsigned bh1 = *(unsigned*)&Whi[n * LDA + kc + 8 + tg2];
            unsigned bl0 = *(unsigned*)&Wlo[n * LDA + kc     + tg2];
            unsigned bl1 = *(unsigned*)&Wlo[n * LDA + kc + 8 + tg2];
            mma16816(c[nt], ah,  bh0, bh1);
            mma16816(c[nt], ah,  bl0, bl1);
            mma16816(c[nt], alr, bh0, bh1);
        }
    }

    __syncwarp();
    #pragma unroll
    for (int nt = 0; nt < 16; nt++) {
        int ncol = nt * 8 + tg2;
        Cst[ g      * LDC + ncol]     = c[nt][0];
        Cst[ g      * LDC + ncol + 1] = c[nt][1];
        Cst[(g + 8) * LDC + ncol]     = c[nt][2];
        Cst[(g + 8) * LDC + ncol + 1] = c[nt][3];
    }
    __syncwarp();

    float4 al4 = ((const float4*)al)[lane];
    float4 ar4 = ((const float4*)ar)[lane];
    int head = lane >> 3;
    #pragma unroll 4
    for (int r = 0; r < 16; r++) {
        int n = nb + r;
        if (n >= NN) break;
        float4 hv = *(float4*)&Cst[r * LDC + lane * 4];
        float pel = hv.x * al4.x + hv.y * al4.y + hv.z * al4.z + hv.w * al4.w;
        float per = hv.x * ar4.x + hv.y * ar4.y + hv.z * ar4.z + hv.w * ar4.w;
        #pragma unroll
        for (int o = 1; o < 8; o <<= 1) {
            pel += __shfl_xor_sync(0xffffffffu, pel, o);
            per += __shfl_xor_sync(0xffffffffu, per, o);
        }
        ((float4*)g_h)[n * 32 + lane] = hv;
        if ((lane & 7) == 0) {
            g_el[n * 4 + head] = pel;
            g_er[n * 4 + head] = per;
        }
    }
}

// ---------------- fused softmax + aggregation (R10 best, unchanged) --------------
__global__ void k_agg(const float* __restrict__ bias, float* __restrict__ outExt, int layer2)
{
    int d    = (blockIdx.x * blockDim.x + threadIdx.x) >> 5;
    int lane = threadIdx.x & 31;
    if (d >= NN) return;
    int hq = lane >> 3;
    int p0 = g_off[d], p1 = g_cur[d];

    float er_h = g_er[d * 4 + hq];

    float sA = 0.f, sB = 0.f;
    float2 A0 = make_float2(0.f, 0.f), A1 = A0, B0 = A0, B1 = A0;

    int p = p0;
    int na = 0, nb = 0;
    if (p + 2 <= p1) { na = g_srcs[p]; nb = g_srcs[p + 1]; }
    while (p + 2 <= p1) {
        int np = p + 2;
        int nna = 0, nnb = 0;
        if (np + 2 <= p1) { nna = g_srcs[np]; nnb = g_srcs[np + 1]; }
        float eA = g_el[na * 4 + hq] + er_h;
        float eB = g_el[nb * 4 + hq] + er_h;
        float4 hA = ((const float4*)g_h)[na * 32 + lane];
        float4 hB = ((const float4*)g_h)[nb * 32 + lane];
        eA = (eA > 0.f) ? eA : NEG * eA;
        eB = (eB > 0.f) ? eB : NEG * eB;
        float xA = __expf(fminf(eA, 80.f));
        float xB = __expf(fminf(eB, 80.f));
        sA += xA; sB += xB;
        float2 dA = dup(xA), dB = dup(xB);
        ffma2(A0, make_float2(hA.x, hA.y), dA);
        ffma2(A1, make_float2(hA.z, hA.w), dA);
        ffma2(B0, make_float2(hB.x, hB.y), dB);
        ffma2(B1, make_float2(hB.z, hB.w), dB);
        na = nna; nb = nnb; p = np;
    }
    if (p < p1) {
        int nc = g_srcs[p];
        float eA = g_el[nc * 4 + hq] + er_h;
        float4 hA = ((const float4*)g_h)[nc * 32 + lane];
        eA = (eA > 0.f) ? eA : NEG * eA;
        float xA = __expf(fminf(eA, 80.f));
        sA += xA;
        float2 dA = dup(xA);
        ffma2(A0, make_float2(hA.x, hA.y), dA);
        ffma2(A1, make_float2(hA.z, hA.w), dA);
    }

    float s = sA + sB;
    float inv = (s > 0.f) ? (1.f / s) : 0.f;
    float a0 = (A0.x + B0.x) * inv;
    float a1 = (A0.y + B0.y) * inv;
    float a2 = (A1.x + B1.x) * inv;
    float a3 = (A1.y + B1.y) * inv;

    if (!layer2) {
        float4 b = ((const float4*)bias)[lane];
        a0 = fmaxf(a0 + b.x, 0.f); a1 = fmaxf(a1 + b.y, 0.f);
        a2 = fmaxf(a2 + b.z, 0.f); a3 = fmaxf(a3 + b.w, 0.f);
        ((float4*)g_x2)[d * 32 + lane] = make_float4(a0, a1, a2, a3);
    } else {
        float4 b = ((const float4*)bias)[lane];
        a0 += b.x; a1 += b.y; a2 += b.z; a3 += b.w;
        a0 += __shfl_xor_sync(0xffffffffu, a0, 8);  a0 += __shfl_xor_sync(0xffffffffu, a0, 16);
        a1 += __shfl_xor_sync(0xffffffffu, a1, 8);  a1 += __shfl_xor_sync(0xffffffffu, a1, 16);
        a2 += __shfl_xor_sync(0xffffffffu, a2, 8);  a2 += __shfl_xor_sync(0xffffffffu, a2, 16);
        a3 += __shfl_xor_sync(0xffffffffu, a3, 8);  a3 += __shfl_xor_sync(0xffffffffu, a3, 16);
        if (lane < 8)
            ((float4*)outExt)[d * 8 + lane] =
                make_float4(0.25f * a0, 0.25f * a1, 0.25f * a2, 0.25f * a3);
    }
}

// ---------------- launch (fork-join: CSR build overlaps wprep+GEMM1) -------------
extern "C" void kernel_launch(void* const* d_in, const int* in_sizes, int n_in,
                              void* d_out, int out_size)
{
    const float* feat = (const float*)d_in[0];
    const int*   src  = (const int*)  d_in[1];
    const int*   dst  = (const int*)  d_in[2];
    const float* W1   = (const float*)d_in[3];
    const float* al1  = (const float*)d_in[4];
    const float* ar1  = (const float*)d_in[5];
    const float* b1   = (const float*)d_in[6];
    const float* W2   = (const float*)d_in[7];
    const float* al2  = (const float*)d_in[8];
    const float* ar2  = (const float*)d_in[9];
    const float* b2   = (const float*)d_in[10];
    float* out = (float*)d_out;

    static cudaStream_t s2 = nullptr;
    static cudaEvent_t eFork = nullptr, eJoin = nullptr;
    if (!s2) {   // one-time host-side resource setup (no device memory)
        cudaStreamCreateWithFlags(&s2, cudaStreamNonBlocking);
        cudaEventCreateWithFlags(&eFork, cudaEventDisableTiming);
        cudaEventCreateWithFlags(&eJoin, cudaEventDisableTiming);
        cudaFuncSetAttribute(k_gemm_tc, cudaFuncAttributeMaxDynamicSharedMemorySize, SMEM_TOTAL);
    }

    // fork: CSR build chain on s2
    cudaEventRecord(eFork, 0);
    cudaStreamWaitEvent(s2, eFork, 0);
    k_zero <<<(NN + 255) / 256, 256, 0, s2>>>();
    k_count<<<(EE / 4 + 255) / 256, 256, 0, s2>>>(dst);
    k_off  <<<(NN + 255) / 256, 256, 0, s2>>>();
    k_fill <<<(EE / 4 + 255) / 256, 256, 0, s2>>>(src, dst);
    cudaEventRecord(eJoin, s2);

    // main stream: W prep + layer-1 GEMM (independent of CSR)
    k_wprep<<<128, 256>>>(W1, W2);
    int gblocks = (NN + 127) / 128;
    k_gemm_tc<<<gblocks, 256, SMEM_TOTAL>>>(feat, 1, 0, al1, ar1);

    // join: agg1 needs both CSR and GEMM1 results
    cudaStreamWaitEvent(0, eJoin, 0);
    k_agg <<<(NN * 32 + 255) / 256, 256>>>(b1, nullptr, 0);

    // layer 2
    k_gemm_tc<<<gblocks, 256, SMEM_TOTAL>>>(nullptr, 0, 1, al2, ar2);
    k_agg <<<(NN * 32 + 255) / 256, 256>>>(b2, out, 1);
}

// round 13
// speedup vs baseline: 1.2786x; 1.0070x over previous
#include <cuda_runtime.h>
#include <cuda_bf16.h>

#define NN 100000
#define EE 800000
#define NEG 0.2f

#define LDA 136          // padded row stride (bf16) for A/W smem tiles
#define LDC 132          // padded row stride (f32) for C staging
#define W_TILE_BYTES (128 * LDA * 2)          // 34816
#define AW_BYTES     (2 * 16 * LDA * 2)       // 8704 per warp (hi+lo)
#define SMEM_TOTAL   (2 * W_TILE_BYTES + 8 * AW_BYTES)   // 139264
#define NTILES ((NN + 127) / 128)

// ---------------- scratch (device globals; no allocation allowed) ----------------
__device__ __align__(16) float g_h [NN * 128];
__device__ __align__(16) float g_x2[NN * 128];
__device__ __align__(16) float g_el[NN * 4];
__device__ __align__(16) float g_er[NN * 4];
__device__ int g_deg [NN];
__device__ int g_off [NN];
__device__ int g_cur [NN];
__device__ int g_srcs[EE];
__device__ int g_tot;
__device__ __align__(4) __nv_bfloat16 g_wthi[2 * 16384];  // Wt hi, [layer][n][k]
__device__ __align__(4) __nv_bfloat16 g_wtlo[2 * 16384];  // Wt lo

// packed f32x2 FMA (agg kernel)
__device__ __forceinline__ void ffma2(float2& d, float2 a, float2 b) {
    asm("fma.rn.f32x2 %0, %1, %2, %0;"
        : "+l"(reinterpret_cast<unsigned long long&>(d))
        : "l"(reinterpret_cast<const unsigned long long&>(a)),
          "l"(reinterpret_cast<const unsigned long long&>(b)));
}
__device__ __forceinline__ float2 dup(float x) { return make_float2(x, x); }

// bf16 hi/lo split of a float2, packed as 2x uint32 (bf16x2)
__device__ __forceinline__ void bf16split(float2 v, unsigned& hi, unsigned& lo) {
    __nv_bfloat162 h = __float22bfloat162_rn(v);
    float2 hf = __bfloat1622float2(h);
    __nv_bfloat162 l = __float22bfloat162_rn(make_float2(v.x - hf.x, v.y - hf.y));
    hi = *reinterpret_cast<unsigned*>(&h);
    lo = *reinterpret_cast<unsigned*>(&l);
}

__device__ __forceinline__ void mma16816(float* c, const unsigned* a, unsigned b0, unsigned b1) {
    asm volatile(
        "mma.sync.aligned.m16n8k16.row.col.f32.bf16.bf16.f32 "
        "{%0,%1,%2,%3},{%4,%5,%6,%7},{%8,%9},{%0,%1,%2,%3};"
        : "+f"(c[0]), "+f"(c[1]), "+f"(c[2]), "+f"(c[3])
        : "r"(a[0]), "r"(a[1]), "r"(a[2]), "r"(a[3]), "r"(b0), "r"(b1));
}

// ---------------- CSR build (scan-free, compact; int4-vectorized) ----------------
__global__ void k_zero() {
    int i = blockIdx.x * blockDim.x + threadIdx.x;
    if (i < NN) g_deg[i] = 0;
    if (i == 0) g_tot = 0;
}

__global__ void k_count(const int* __restrict__ dst) {
    int e = blockIdx.x * blockDim.x + threadIdx.x;
    if (e < EE / 4) {
        int4 d4 = ((const int4*)dst)[e];
        atomicAdd(&g_deg[d4.x], 1);
        atomicAdd(&g_deg[d4.y], 1);
        atomicAdd(&g_deg[d4.z], 1);
        atomicAdd(&g_deg[d4.w], 1);
    }
}

__global__ void k_off() {
    int i = blockIdx.x * blockDim.x + threadIdx.x;
    int lane = threadIdx.x & 31;
    int v = (i < NN) ? g_deg[i] : 0;
    int x = v;
    #pragma unroll
    for (int o = 1; o < 32; o <<= 1) {
        int t = __shfl_up_sync(0xffffffffu, x, o);
        if (lane >= o) x += t;
    }
    int excl = x - v;
    int wsum = __shfl_sync(0xffffffffu, x, 31);
    int base = 0;
    if (lane == 31) base = atomicAdd(&g_tot, wsum);
    base = __shfl_sync(0xffffffffu, base, 31);
    if (i < NN) {
        g_off[i] = base + excl;
        g_cur[i] = base + excl;
    }
}

__global__ void k_fill(const int* __restrict__ src, const int* __restrict__ dst) {
    int e = blockIdx.x * blockDim.x + threadIdx.x;
    if (e < EE / 4) {
        int4 d4 = ((const int4*)dst)[e];
        int4 s4 = ((const int4*)src)[e];
        g_srcs[atomicAdd(&g_cur[d4.x], 1)] = s4.x;
        g_srcs[atomicAdd(&g_cur[d4.y], 1)] = s4.y;
        g_srcs[atomicAdd(&g_cur[d4.z], 1)] = s4.z;
        g_srcs[atomicAdd(&g_cur[d4.w], 1)] = s4.w;
    }
}

// ---------------- W prep: transpose + bf16 hi/lo split, both layers ----------------
__global__ void k_wprep(const float* __restrict__ W1, const float* __restrict__ W2) {
    int i = blockIdx.x * 256 + threadIdx.x;
    if (i < 32768) {
        int l = i >> 14, j = i & 16383;
        int n = j >> 7, k = j & 127;
        float x = (l ? W2 : W1)[k * 128 + n];
        __nv_bfloat16 h = __float2bfloat16_rn(x);
        g_wthi[i] = h;
        g_wtlo[i] = __float2bfloat16_rn(x - __bfloat162float(h));
    }
}

// ---------------- tensor-core GEMM + epilogue (persistent grid-stride) -----------
__global__ void k_gemm_tc(const float* __restrict__ Xext, int useExt, int layer,
                          const float* __restrict__ al, const float* __restrict__ ar)
{
    extern __shared__ char sm[];
    __nv_bfloat16* Whi = (__nv_bfloat16*)sm;
    __nv_bfloat16* Wlo = Whi + 128 * LDA;
    const float* X = useExt ? Xext : g_x2;

    int tid = threadIdx.x;
    int w = tid >> 5, lane = tid & 31;
    char* abase = sm + 2 * W_TILE_BYTES + w * AW_BYTES;
    __nv_bfloat16* Ahi = (__nv_bfloat16*)abase;
    __nv_bfloat16* Alo = Ahi + 16 * LDA;
    float* Cst = (float*)abase;

    // stage W once per block (persistent)
    const __nv_bfloat16* gwh = g_wthi + layer * 16384;
    const __nv_bfloat16* gwl = g_wtlo + layer * 16384;
    for (int i = tid; i < 16384; i += 256) {
        int n = i >> 7, k = i & 127;
        Whi[n * LDA + k] = gwh[i];
        Wlo[n * LDA + k] = gwl[i];
    }
    __syncthreads();

    float4 al4 = ((const float4*)al)[lane];
    float4 ar4 = ((const float4*)ar)[lane];
    int head = lane >> 3;
    int g = lane >> 2, tg2 = (lane & 3) * 2;

    for (int tile = blockIdx.x; tile < NTILES; tile += gridDim.x) {
        int nb = tile * 128 + w * 16;

        #pragma unroll 4
        for (int r = 0; r < 16; r++) {
            int n = nb + r;
            float4 v = (n < NN) ? ((const float4*)X)[n * 32 + lane]
                                : make_float4(0.f, 0.f, 0.f, 0.f);
            unsigned h01, l01, h23, l23;
            bf16split(make_float2(v.x, v.y), h01, l01);
            bf16split(make_float2(v.z, v.w), h23, l23);
            *(unsigned*)&Ahi[r * LDA + lane * 4]     = h01;
            *(unsigned*)&Ahi[r * LDA + lane * 4 + 2] = h23;
            *(unsigned*)&Alo[r * LDA + lane * 4]     = l01;
            *(unsigned*)&Alo[r * LDA + lane * 4 + 2] = l23;
        }
        __syncwarp();   // A region is per-warp

        float c[16][4];
        #pragma unroll
        for (int nt = 0; nt < 16; nt++)
            c[nt][0] = c[nt][1] = c[nt][2] = c[nt][3] = 0.f;

        #pragma unroll
        for (int ks = 0; ks < 8; ks++) {
            int kc = ks * 16;
            unsigned ah[4], alr[4];
            ah[0]  = *(unsigned*)&Ahi[ g      * LDA + kc     + tg2];
            ah[1]  = *(unsigned*)&Ahi[(g + 8) * LDA + kc     + tg2];
            ah[2]  = *(unsigned*)&Ahi[ g      * LDA + kc + 8 + tg2];
            ah[3]  = *(unsigned*)&Ahi[(g + 8) * LDA + kc + 8 + tg2];
            alr[0] = *(unsigned*)&Alo[ g      * LDA + kc     + tg2];
            alr[1] = *(unsigned*)&Alo[(g + 8) * LDA + kc     + tg2];
            alr[2] = *(unsigned*)&Alo[ g      * LDA + kc + 8 + tg2];
            alr[3] = *(unsigned*)&Alo[(g + 8) * LDA + kc + 8 + tg2];
            #pragma unroll
            for (int nt = 0; nt < 16; nt++) {
                int n = nt * 8 + g;
                unsigned bh0 = *(unsigned*)&Whi[n * LDA + kc     + tg2];
                unsigned bh1 = *(unsigned*)&Whi[n * LDA + kc + 8 + tg2];
                unsigned bl0 = *(unsigned*)&Wlo[n * LDA + kc     + tg2];
                unsigned bl1 = *(unsigned*)&Wlo[n * LDA + kc + 8 + tg2];
                mma16816(c[nt], ah,  bh0, bh1);
                mma16816(c[nt], ah,  bl0, bl1);
                mma16816(c[nt], alr, bh0, bh1);
            }
        }

        __syncwarp();
        #pragma unroll
        for (int nt = 0; nt < 16; nt++) {
            int ncol = nt * 8 + tg2;
            Cst[ g      * LDC + ncol]     = c[nt][0];
            Cst[ g      * LDC + ncol + 1] = c[nt][1];
            Cst[(g + 8) * LDC + ncol]     = c[nt][2];
            Cst[(g + 8) * LDC + ncol + 1] = c[nt][3];
        }
        __syncwarp();

        #pragma unroll 4
        for (int r = 0; r < 16; r++) {
            int n = nb + r;
            if (n >= NN) continue;
            float4 hv = *(float4*)&Cst[r * LDC + lane * 4];
            float pel = hv.x * al4.x + hv.y * al4.y + hv.z * al4.z + hv.w * al4.w;
            float per = hv.x * ar4.x + hv.y * ar4.y + hv.z * ar4.z + hv.w * ar4.w;
            #pragma unroll
            for (int o = 1; o < 8; o <<= 1) {
                pel += __shfl_xor_sync(0xffffffffu, pel, o);
                per += __shfl_xor_sync(0xffffffffu, per, o);
            }
            ((float4*)g_h)[n * 32 + lane] = hv;
            if ((lane & 7) == 0) {
                g_el[n * 4 + head] = pel;
                g_er[n * 4 + head] = per;
            }
        }
        __syncwarp();   // Cst reused as A staging next tile
    }
}

// ---------------- fused softmax + aggregation: TWO dst nodes per warp ------------
// Warp walks both nodes' edge lists simultaneously, 2-wide each -> 4 independent
// 512B h-gathers in flight per warp. Tail predicated (@!P skips the load).
// Normalization deferred; no max-subtraction (logits O(1); fminf guard no-op).
__global__ void k_agg(const float* __restrict__ bias, float* __restrict__ outExt, int layer2)
{
    int pr   = (blockIdx.x * blockDim.x + threadIdx.x) >> 5;  // node pair id
    int lane = threadIdx.x & 31;
    int u = pr * 2, v = u + 1;
    if (u >= NN) return;
    bool hasV = (v < NN);
    int hq = lane >> 3;

    int pu = g_off[u], pu1 = g_cur[u];
    int pv = 0, pv1 = 0;
    if (hasV) { pv = g_off[v]; pv1 = g_cur[v]; }
    float erU = g_er[u * 4 + hq];
    float erV = hasV ? g_er[v * 4 + hq] : 0.f;

    float sU = 0.f, sV = 0.f;
    float2 U0 = make_float2(0.f, 0.f), U1 = U0, U2 = U0, U3 = U0;
    float2 V0 = U0, V1 = U0, V2 = U0, V3 = U0;

    while (pu < pu1 || pv < pv1) {
        bool ua = pu < pu1,     ub = pu + 1 < pu1;
        bool va = pv < pv1,     vb = pv + 1 < pv1;
        int nua = ua ? g_srcs[pu]     : 0;
        int nub = ub ? g_srcs[pu + 1] : 0;
        int nva = va ? g_srcs[pv]     : 0;
        int nvb = vb ? g_srcs[pv + 1] : 0;
        float eua = ua ? g_el[nua * 4 + hq] + erU : -1e9f;
        float eub = ub ? g_el[nub * 4 + hq] + erU : -1e9f;
        float eva = va ? g_el[nva * 4 + hq] + erV : -1e9f;
        float evb = vb ? g_el[nvb * 4 + hq] + erV : -1e9f;
        float4 z = make_float4(0.f, 0.f, 0.f, 0.f);
        float4 hua = ua ? ((const float4*)g_h)[nua * 32 + lane] : z;
        float4 hub = ub ? ((const float4*)g_h)[nub * 32 + lane] : z;
        float4 hva = va ? ((const float4*)g_h)[nva * 32 + lane] : z;
        float4 hvb = vb ? ((const float4*)g_h)[nvb * 32 + lane] : z;
        eua = (eua > 0.f) ? eua : NEG * eua;
        eub = (eub > 0.f) ? eub : NEG * eub;
        eva = (eva > 0.f) ? eva : NEG * eva;
        evb = (evb > 0.f) ? evb : NEG * evb;
        float xua = ua ? __expf(fminf(eua, 80.f)) : 0.f;
        float xub = ub ? __expf(fminf(eub, 80.f)) : 0.f;
        float xva = va ? __expf(fminf(eva, 80.f)) : 0.f;
        float xvb = vb ? __expf(fminf(evb, 80.f)) : 0.f;
        sU += xua + xub;  sV += xva + xvb;
        float2 da = dup(xua), db = dup(xub), dc = dup(xva), dd = dup(xvb);
        ffma2(U0, make_float2(hua.x, hua.y), da); ffma2(U1, make_float2(hua.z, hua.w), da);
        ffma2(U2, make_float2(hub.x, hub.y), db); ffma2(U3, make_float2(hub.z, hub.w), db);
        ffma2(V0, make_float2(hva.x, hva.y), dc); ffma2(V1, make_float2(hva.z, hva.w), dc);
        ffma2(V2, make_float2(hvb.x, hvb.y), dd); ffma2(V3, make_float2(hvb.z, hvb.w), dd);
        pu += 2; pv += 2;
    }

    float4 b = ((const float4*)bias)[lane];
    #pragma unroll
    for (int side = 0; side < 2; side++) {
        int d = side ? v : u;
        if (side && !hasV) break;
        float s = side ? sV : sU;
        float inv = (s > 0.f) ? (1.f / s) : 0.f;
        float a0 = (side ? (V0.x + V2.x) : (U0.x + U2.x)) * inv;
        float a1 = (side ? (V0.y + V2.y) : (U0.y + U2.y)) * inv;
        float a2 = (side ? (V1.x + V3.x) : (U1.x + U3.x)) * inv;
        float a3 = (side ? (V1.y + V3.y) : (U1.y + U3.y)) * inv;
        if (!layer2) {
            float r0 = fmaxf(a0 + b.x, 0.f), r1 = fmaxf(a1 + b.y, 0.f);
            float r2 = fmaxf(a2 + b.z, 0.f), r3 = fmaxf(a3 + b.w, 0.f);
            ((float4*)g_x2)[d * 32 + lane] = make_float4(r0, r1, r2, r3);
        } else {
            a0 += b.x; a1 += b.y; a2 += b.z; a3 += b.w;
            a0 += __shfl_xor_sync(0xffffffffu, a0, 8);  a0 += __shfl_xor_sync(0xffffffffu, a0, 16);
            a1 += __shfl_xor_sync(0xffffffffu, a1, 8);  a1 += __shfl_xor_sync(0xffffffffu, a1, 16);
            a2 += __shfl_xor_sync(0xffffffffu, a2, 8);  a2 += __shfl_xor_sync(0xffffffffu, a2, 16);
            a3 += __shfl_xor_sync(0xffffffffu, a3, 8);  a3 += __shfl_xor_sync(0xffffffffu, a3, 16);
            if (lane < 8)
                ((float4*)outExt)[d * 8 + lane] =
                    make_float4(0.25f * a0, 0.25f * a1, 0.25f * a2, 0.25f * a3);
        }
    }
}

// ---------------- launch (fork-join: CSR build overlaps wprep+GEMM1) -------------
extern "C" void kernel_launch(void* const* d_in, const int* in_sizes, int n_in,
                              void* d_out, int out_size)
{
    const float* feat = (const float*)d_in[0];
    const int*   src  = (const int*)  d_in[1];
    const int*   dst  = (const int*)  d_in[2];
    const float* W1   = (const float*)d_in[3];
    const float* al1  = (const float*)d_in[4];
    const float* ar1  = (const float*)d_in[5];
    const float* b1   = (const float*)d_in[6];
    const float* W2   = (const float*)d_in[7];
    const float* al2  = (const float*)d_in[8];
    const float* ar2  = (const float*)d_in[9];
    const float* b2   = (const float*)d_in[10];
    float* out = (float*)d_out;

    static cudaStream_t s2 = nullptr;
    static cudaEvent_t eFork = nullptr, eJoin = nullptr;
    if (!s2) {
        cudaStreamCreateWithFlags(&s2, cudaStreamNonBlocking);
        cudaEventCreateWithFlags(&eFork, cudaEventDisableTiming);
        cudaEventCreateWithFlags(&eJoin, cudaEventDisableTiming);
        cudaFuncSetAttribute(k_gemm_tc, cudaFuncAttributeMaxDynamicSharedMemorySize, SMEM_TOTAL);
    }

    // fork: CSR build chain on s2
    cudaEventRecord(eFork, 0);
    cudaStreamWaitEvent(s2, eFork, 0);
    k_zero <<<(NN + 255) / 256, 256, 0, s2>>>();
    k_count<<<(EE / 4 + 255) / 256, 256, 0, s2>>>(dst);
    k_off  <<<(NN + 255) / 256, 256, 0, s2>>>();
    k_fill <<<(EE / 4 + 255) / 256, 256, 0, s2>>>(src, dst);
    cudaEventRecord(eJoin, s2);

    // main stream: W prep + layer-1 GEMM (independent of CSR)
    k_wprep<<<128, 256>>>(W1, W2);
    k_gemm_tc<<<148, 256, SMEM_TOTAL>>>(feat, 1, 0, al1, ar1);

    // join: agg1 needs both CSR and GEMM1 results
    cudaStreamWaitEvent(0, eJoin, 0);
    int aggblocks = ((NN + 1) / 2 * 32 + 255) / 256;
    k_agg <<<aggblocks, 256>>>(b1, nullptr, 0);

    // layer 2
    k_gemm_tc<<<148, 256, SMEM_TOTAL>>>(nullptr, 0, 1, al2, ar2);
    k_agg <<<aggblocks, 256>>>(b2, out, 1);
}

// round 15
// speedup vs baseline: 1.3772x; 1.0771x over previous
#include <cuda_runtime.h>
#include <cuda_bf16.h>
#include <cuda_fp16.h>

#define NN 100000
#define EE 800000
#define NEG 0.2f

#define LDA 136          // padded row stride (bf16) for A/W smem tiles
#define LDC 132          // padded row stride (f32) for C staging
#define W_TILE_BYTES (128 * LDA * 2)          // 34816
#define AW_BYTES     (2 * 16 * LDA * 2)       // 8704 per warp (hi+lo)
#define SMEM_TOTAL   (2 * W_TILE_BYTES + 8 * AW_BYTES)   // 139264
#define NTILES ((NN + 127) / 128)

// ---------------- scratch (device globals; no allocation allowed) ----------------
__device__ __align__(16) unsigned g_hh[NN * 64];   // h in packed half2 ([n][128] halfs)
__device__ __align__(16) float g_x2[NN * 128];     // layer-1 output (fp32, GEMM2 input)
__device__ __align__(16) float g_el[NN * 4];
__device__ __align__(16) float g_er[NN * 4];
__device__ int g_deg [NN];
__device__ int g_off [NN];
__device__ int g_cur [NN];
__device__ int g_srcs[EE];
__device__ int g_tot;
__device__ __align__(4) __nv_bfloat16 g_wthi[2 * 16384];  // Wt hi, [layer][n][k]
__device__ __align__(4) __nv_bfloat16 g_wtlo[2 * 16384];  // Wt lo

// packed f32x2 FMA (agg kernel)
__device__ __forceinline__ void ffma2(float2& d, float2 a, float2 b) {
    asm("fma.rn.f32x2 %0, %1, %2, %0;"
        : "+l"(reinterpret_cast<unsigned long long&>(d))
        : "l"(reinterpret_cast<const unsigned long long&>(a)),
          "l"(reinterpret_cast<const unsigned long long&>(b)));
}
__device__ __forceinline__ float2 dup(float x) { return make_float2(x, x); }

// bf16 hi/lo split of a float2, packed as 2x uint32 (bf16x2)
__device__ __forceinline__ void bf16split(float2 v, unsigned& hi, unsigned& lo) {
    __nv_bfloat162 h = __float22bfloat162_rn(v);
    float2 hf = __bfloat1622float2(h);
    __nv_bfloat162 l = __float22bfloat162_rn(make_float2(v.x - hf.x, v.y - hf.y));
    hi = *reinterpret_cast<unsigned*>(&h);
    lo = *reinterpret_cast<unsigned*>(&l);
}

__device__ __forceinline__ void mma16816(float* c, const unsigned* a, unsigned b0, unsigned b1) {
    asm volatile(
        "mma.sync.aligned.m16n8k16.row.col.f32.bf16.bf16.f32 "
        "{%0,%1,%2,%3},{%4,%5,%6,%7},{%8,%9},{%0,%1,%2,%3};"
        : "+f"(c[0]), "+f"(c[1]), "+f"(c[2]), "+f"(c[3])
        : "r"(a[0]), "r"(a[1]), "r"(a[2]), "r"(a[3]), "r"(b0), "r"(b1));
}

// ---------------- CSR build (scan-free, compact; int4-vectorized) ----------------
__global__ void k_zero() {
    int i = blockIdx.x * blockDim.x + threadIdx.x;
    if (i < NN) g_deg[i] = 0;
    if (i == 0) g_tot = 0;
}

__global__ void k_count(const int* __restrict__ dst) {
    int e = blockIdx.x * blockDim.x + threadIdx.x;
    if (e < EE / 4) {
        int4 d4 = ((const int4*)dst)[e];
        atomicAdd(&g_deg[d4.x], 1);
        atomicAdd(&g_deg[d4.y], 1);
        atomicAdd(&g_deg[d4.z], 1);
        atomicAdd(&g_deg[d4.w], 1);
    }
}

__global__ void k_off() {
    int i = blockIdx.x * blockDim.x + threadIdx.x;
    int lane = threadIdx.x & 31;
    int v = (i < NN) ? g_deg[i] : 0;
    int x = v;
    #pragma unroll
    for (int o = 1; o < 32; o <<= 1) {
        int t = __shfl_up_sync(0xffffffffu, x, o);
        if (lane >= o) x += t;
    }
    int excl = x - v;
    int wsum = __shfl_sync(0xffffffffu, x, 31);
    int base = 0;
    if (lane == 31) base = atomicAdd(&g_tot, wsum);
    base = __shfl_sync(0xffffffffu, base, 31);
    if (i < NN) {
        g_off[i] = base + excl;
        g_cur[i] = base + excl;
    }
}

__global__ void k_fill(const int* __restrict__ src, const int* __restrict__ dst) {
    int e = blockIdx.x * blockDim.x + threadIdx.x;
    if (e < EE / 4) {
        int4 d4 = ((const int4*)dst)[e];
        int4 s4 = ((const int4*)src)[e];
        g_srcs[atomicAdd(&g_cur[d4.x], 1)] = s4.x;
        g_srcs[atomicAdd(&g_cur[d4.y], 1)] = s4.y;
        g_srcs[atomicAdd(&g_cur[d4.z], 1)] = s4.z;
        g_srcs[atomicAdd(&g_cur[d4.w], 1)] = s4.w;
    }
}

// ---------------- W prep: transpose + bf16 hi/lo split, both layers ----------------
__global__ void k_wprep(const float* __restrict__ W1, const float* __restrict__ W2) {
    int i = blockIdx.x * 256 + threadIdx.x;
    if (i < 32768) {
        int l = i >> 14, j = i & 16383;
        int n = j >> 7, k = j & 127;
        float x = (l ? W2 : W1)[k * 128 + n];
        __nv_bfloat16 h = __float2bfloat16_rn(x);
        g_wthi[i] = h;
        g_wtlo[i] = __float2bfloat16_rn(x - __bfloat162float(h));
    }
}

// ---------------- tensor-core GEMM + epilogue (persistent grid-stride) -----------
// Epilogue now emits h as packed half2 (g_hh) — agg's only h consumer.
__global__ void k_gemm_tc(const float* __restrict__ Xext, int useExt, int layer,
                          const float* __restrict__ al, const float* __restrict__ ar)
{
    extern __shared__ char sm[];
    __nv_bfloat16* Whi = (__nv_bfloat16*)sm;
    __nv_bfloat16* Wlo = Whi + 128 * LDA;
    const float* X = useExt ? Xext : g_x2;

    int tid = threadIdx.x;
    int w = tid >> 5, lane = tid & 31;
    char* abase = sm + 2 * W_TILE_BYTES + w * AW_BYTES;
    __nv_bfloat16* Ahi = (__nv_bfloat16*)abase;
    __nv_bfloat16* Alo = Ahi + 16 * LDA;
    float* Cst = (float*)abase;

    const __nv_bfloat16* gwh = g_wthi + layer * 16384;
    const __nv_bfloat16* gwl = g_wtlo + layer * 16384;
    for (int i = tid; i < 16384; i += 256) {
        int n = i >> 7, k = i & 127;
        Whi[n * LDA + k] = gwh[i];
        Wlo[n * LDA + k] = gwl[i];
    }
    __syncthreads();

    float4 al4 = ((const float4*)al)[lane];
    float4 ar4 = ((const float4*)ar)[lane];
    int head = lane >> 3;
    int g = lane >> 2, tg2 = (lane & 3) * 2;

    for (int tile = blockIdx.x; tile < NTILES; tile += gridDim.x) {
        int nb = tile * 128 + w * 16;

        #pragma unroll 4
        for (int r = 0; r < 16; r++) {
            int n = nb + r;
            float4 v = (n < NN) ? ((const float4*)X)[n * 32 + lane]
                                : make_float4(0.f, 0.f, 0.f, 0.f);
            unsigned h01, l01, h23, l23;
            bf16split(make_float2(v.x, v.y), h01, l01);
            bf16split(make_float2(v.z, v.w), h23, l23);
            *(unsigned*)&Ahi[r * LDA + lane * 4]     = h01;
            *(unsigned*)&Ahi[r * LDA + lane * 4 + 2] = h23;
            *(unsigned*)&Alo[r * LDA + lane * 4]     = l01;
            *(unsigned*)&Alo[r * LDA + lane * 4 + 2] = l23;
        }
        __syncwarp();

        float c[16][4];
        #pragma unroll
        for (int nt = 0; nt < 16; nt++)
            c[nt][0] = c[nt][1] = c[nt][2] = c[nt][3] = 0.f;

        #pragma unroll
        for (int ks = 0; ks < 8; ks++) {
            int kc = ks * 16;
            unsigned ah[4], alr[4];
            ah[0]  = *(unsigned*)&Ahi[ g      * LDA + kc     + tg2];
            ah[1]  = *(unsigned*)&Ahi[(g + 8) * LDA + kc     + tg2];
            ah[2]  = *(unsigned*)&Ahi[ g      * LDA + kc + 8 + tg2];
            ah[3]  = *(unsigned*)&Ahi[(g + 8) * LDA + kc + 8 + tg2];
            alr[0] = *(unsigned*)&Alo[ g      * LDA + kc     + tg2];
            alr[1] = *(unsigned*)&Alo[(g + 8) * LDA + kc     + tg2];
            alr[2] = *(unsigned*)&Alo[ g      * LDA + kc + 8 + tg2];
            alr[3] = *(unsigned*)&Alo[(g + 8) * LDA + kc + 8 + tg2];
            #pragma unroll
            for (int nt = 0; nt < 16; nt++) {
                int n = nt * 8 + g;
                unsigned bh0 = *(unsigned*)&Whi[n * LDA + kc     + tg2];
                unsigned bh1 = *(unsigned*)&Whi[n * LDA + kc + 8 + tg2];
                unsigned bl0 = *(unsigned*)&Wlo[n * LDA + kc     + tg2];
                unsigned bl1 = *(unsigned*)&Wlo[n * LDA + kc + 8 + tg2];
                mma16816(c[nt], ah,  bh0, bh1);
                mma16816(c[nt], ah,  bl0, bl1);
                mma16816(c[nt], alr, bh0, bh1);
            }
        }

        __syncwarp();
        #pragma unroll
        for (int nt = 0; nt < 16; nt++) {
            int ncol = nt * 8 + tg2;
            Cst[ g      * LDC + ncol]     = c[nt][0];
            Cst[ g      * LDC + ncol + 1] = c[nt][1];
            Cst[(g + 8) * LDC + ncol]     = c[nt][2];
            Cst[(g + 8) * LDC + ncol + 1] = c[nt][3];
        }
        __syncwarp();

        #pragma unroll 4
        for (int r = 0; r < 16; r++) {
            int n = nb + r;
            if (n >= NN) continue;
            float4 hv = *(float4*)&Cst[r * LDC + lane * 4];
            float pel = hv.x * al4.x + hv.y * al4.y + hv.z * al4.z + hv.w * al4.w;
            float per = hv.x * ar4.x + hv.y * ar4.y + hv.z * ar4.z + hv.w * ar4.w;
            #pragma unroll
            for (int o = 1; o < 8; o <<= 1) {
                pel += __shfl_xor_sync(0xffffffffu, pel, o);
                per += __shfl_xor_sync(0xffffffffu, per, o);
            }
            // h emitted as packed half2 only (halves agg gather traffic)
            __half2 p0 = __floats2half2_rn(hv.x, hv.y);
            __half2 p1 = __floats2half2_rn(hv.z, hv.w);
            uint2 pk = make_uint2(*reinterpret_cast<unsigned*>(&p0),
                                  *reinterpret_cast<unsigned*>(&p1));
            ((uint2*)g_hh)[n * 32 + lane] = pk;
            if ((lane & 7) == 0) {
                g_el[n * 4 + head] = pel;
                g_er[n * 4 + head] = per;
            }
        }
        __syncwarp();
    }
}

// ---------------- fused softmax + aggregation: TWO dst nodes per warp ------------
// h gathered as packed half2 (256B per warp per edge — half the fp32 traffic).
// fp32 accumulation; normalization deferred; no max-subtraction (logits O(1)).
__global__ void k_agg(const float* __restrict__ bias, float* __restrict__ outExt, int layer2)
{
    int pr   = (blockIdx.x * blockDim.x + threadIdx.x) >> 5;
    int lane = threadIdx.x & 31;
    int u = pr * 2, v = u + 1;
    if (u >= NN) return;
    bool hasV = (v < NN);
    int hq = lane >> 3;

    int pu = g_off[u], pu1 = g_cur[u];
    int pv = 0, pv1 = 0;
    if (hasV) { pv = g_off[v]; pv1 = g_cur[v]; }
    float erU = g_er[u * 4 + hq];
    float erV = hasV ? g_er[v * 4 + hq] : 0.f;

    float sU = 0.f, sV = 0.f;
    float2 U0 = make_float2(0.f, 0.f), U1 = U0, U2 = U0, U3 = U0;
    float2 V0 = U0, V1 = U0, V2 = U0, V3 = U0;
    const uint2* hh = (const uint2*)g_hh;

    while (pu < pu1 || pv < pv1) {
        bool ua = pu < pu1,     ub = pu + 1 < pu1;
        bool va = pv < pv1,     vb = pv + 1 < pv1;
        int nua = ua ? g_srcs[pu]     : 0;
        int nub = ub ? g_srcs[pu + 1] : 0;
        int nva = va ? g_srcs[pv]     : 0;
        int nvb = vb ? g_srcs[pv + 1] : 0;
        float eua = ua ? g_el[nua * 4 + hq] + erU : -1e9f;
        float eub = ub ? g_el[nub * 4 + hq] + erU : -1e9f;
        float eva = va ? g_el[nva * 4 + hq] + erV : -1e9f;
        float evb = vb ? g_el[nvb * 4 + hq] + erV : -1e9f;
        uint2 z2 = make_uint2(0u, 0u);
        uint2 qua = ua ? hh[nua * 32 + lane] : z2;
        uint2 qub = ub ? hh[nub * 32 + lane] : z2;
        uint2 qva = va ? hh[nva * 32 + lane] : z2;
        uint2 qvb = vb ? hh[nvb * 32 + lane] : z2;
        eua = (eua > 0.f) ? eua : NEG * eua;
        eub = (eub > 0.f) ? eub : NEG * eub;
        eva = (eva > 0.f) ? eva : NEG * eva;
        evb = (evb > 0.f) ? evb : NEG * evb;
        float xua = ua ? __expf(fminf(eua, 80.f)) : 0.f;
        float xub = ub ? __expf(fminf(eub, 80.f)) : 0.f;
        float xva = va ? __expf(fminf(eva, 80.f)) : 0.f;
        float xvb = vb ? __expf(fminf(evb, 80.f)) : 0.f;
        sU += xua + xub;  sV += xva + xvb;
        float2 da = dup(xua), db = dup(xub), dc = dup(xva), dd = dup(xvb);
        ffma2(U0, __half22float2(*(__half2*)&qua.x), da);
        ffma2(U1, __half22float2(*(__half2*)&qua.y), da);
        ffma2(U2, __half22float2(*(__half2*)&qub.x), db);
        ffma2(U3, __half22float2(*(__half2*)&qub.y), db);
        ffma2(V0, __half22float2(*(__half2*)&qva.x), dc);
        ffma2(V1, __half22float2(*(__half2*)&qva.y), dc);
        ffma2(V2, __half22float2(*(__half2*)&qvb.x), dd);
        ffma2(V3, __half22float2(*(__half2*)&qvb.y), dd);
        pu += 2; pv += 2;
    }

    float4 b = ((const float4*)bias)[lane];
    #pragma unroll
    for (int side = 0; side < 2; side++) {
        int d = side ? v : u;
        if (side && !hasV) break;
        float s = side ? sV : sU;
        float inv = (s > 0.f) ? (1.f / s) : 0.f;
        float a0 = (side ? (V0.x + V2.x) : (U0.x + U2.x)) * inv;
        float a1 = (side ? (V0.y + V2.y) : (U0.y + U2.y)) * inv;
        float a2 = (side ? (V1.x + V3.x) : (U1.x + U3.x)) * inv;
        float a3 = (side ? (V1.y + V3.y) : (U1.y + U3.y)) * inv;
        if (!layer2) {
            float r0 = fmaxf(a0 + b.x, 0.f), r1 = fmaxf(a1 + b.y, 0.f);
            float r2 = fmaxf(a2 + b.z, 0.f), r3 = fmaxf(a3 + b.w, 0.f);
            ((float4*)g_x2)[d * 32 + lane] = make_float4(r0, r1, r2, r3);
        } else {
            a0 += b.x; a1 += b.y; a2 += b.z; a3 += b.w;
            a0 += __shfl_xor_sync(0xffffffffu, a0, 8);  a0 += __shfl_xor_sync(0xffffffffu, a0, 16);
            a1 += __shfl_xor_sync(0xffffffffu, a1, 8);  a1 += __shfl_xor_sync(0xffffffffu, a1, 16);
            a2 += __shfl_xor_sync(0xffffffffu, a2, 8);  a2 += __shfl_xor_sync(0xffffffffu, a2, 16);
            a3 += __shfl_xor_sync(0xffffffffu, a3, 8);  a3 += __shfl_xor_sync(0xffffffffu, a3, 16);
            if (lane < 8)
                ((float4*)outExt)[d * 8 + lane] =
                    make_float4(0.25f * a0, 0.25f * a1, 0.25f * a2, 0.25f * a3);
        }
    }
}

// ---------------- launch (fork-join: CSR build overlaps wprep+GEMM1) -------------
extern "C" void kernel_launch(void* const* d_in, const int* in_sizes, int n_in,
                              void* d_out, int out_size)
{
    const float* feat = (const float*)d_in[0];
    const int*   src  = (const int*)  d_in[1];
    const int*   dst  = (const int*)  d_in[2];
    const float* W1   = (const float*)d_in[3];
    const float* al1  = (const float*)d_in[4];
    const float* ar1  = (const float*)d_in[5];
    const float* b1   = (const float*)d_in[6];
    const float* W2   = (const float*)d_in[7];
    const float* al2  = (const float*)d_in[8];
    const float* ar2  = (const float*)d_in[9];
    const float* b2   = (const float*)d_in[10];
    float* out = (float*)d_out;

    static cudaStream_t s2 = nullptr;
    static cudaEvent_t eFork = nullptr, eJoin = nullptr;
    if (!s2) {
        cudaStreamCreateWithFlags(&s2, cudaStreamNonBlocking);
        cudaEventCreateWithFlags(&eFork, cudaEventDisableTiming);
        cudaEventCreateWithFlags(&eJoin, cudaEventDisableTiming);
        cudaFuncSetAttribute(k_gemm_tc, cudaFuncAttributeMaxDynamicSharedMemorySize, SMEM_TOTAL);
    }

    // fork: CSR build chain on s2
    cudaEventRecord(eFork, 0);
    cudaStreamWaitEvent(s2, eFork, 0);
    k_zero <<<(NN + 255) / 256, 256, 0, s2>>>();
    k_count<<<(EE / 4 + 255) / 256, 256, 0, s2>>>(dst);
    k_off  <<<(NN + 255) / 256, 256, 0, s2>>>();
    k_fill <<<(EE / 4 + 255) / 256, 256, 0, s2>>>(src, dst);
    cudaEventRecord(eJoin, s2);

    // main stream: W prep + layer-1 GEMM (independent of CSR)
    k_wprep<<<128, 256>>>(W1, W2);
    k_gemm_tc<<<148, 256, SMEM_TOTAL>>>(feat, 1, 0, al1, ar1);

    // join: agg1 needs both CSR and GEMM1 results
    cudaStreamWaitEvent(0, eJoin, 0);
    int aggblocks = ((NN + 1) / 2 * 32 + 255) / 256;
    k_agg <<<aggblocks, 256>>>(b1, nullptr, 0);

    // layer 2
    k_gemm_tc<<<148, 256, SMEM_TOTAL>>>(nullptr, 0, 1, al2, ar2);
    k_agg <<<aggblocks, 256>>>(b2, out, 1);
}